// round 16
// baseline (speedup 1.0000x reference)
#include <cuda_runtime.h>
#include <cuda_fp16.h>
#include <math.h>
#include <stdint.h>

// Shapes: B=8, H=W=128 -> LT = 131072 rows, C = 128
#define LT 131072

// ---------------- scratch (static device arrays; no allocation) -------------
__device__ __half g_ln [(size_t)LT * 128];
__device__ __half g_qkv[(size_t)LT * 384];
__device__ __half g_att[(size_t)LT * 128];
__device__ float  g_y  [(size_t)LT * 128];
__device__ __half g_ln2[(size_t)LT * 128];
__device__ __half g_h  [(size_t)LT * 512];
__device__ __half g_wq_h[384 * 128];
__device__ __half g_wp_h[128 * 128];
__device__ __half g_w1_h[512 * 128];
__device__ __half g_w2_h[128 * 512];

// ---------------- PTX helpers (sm_80-compatible only) ------------------------
__device__ __forceinline__ uint32_t smem_u32(const void* p) {
    uint32_t a;
    asm("{ .reg .u64 t; cvta.to.shared.u64 t, %1; cvt.u32.u64 %0, t; }" : "=r"(a) : "l"(p));
    return a;
}
__device__ __forceinline__ void cp_async16(uint32_t saddr, const void* gaddr) {
    asm volatile("cp.async.cg.shared.global [%0], [%1], 16;"
                 :: "r"(saddr), "l"(gaddr) : "memory");
}
#define CP_COMMIT() asm volatile("cp.async.commit_group;" ::: "memory")
#define CP_WAIT2()  asm volatile("cp.async.wait_group 2;" ::: "memory")
#define CP_WAIT1()  asm volatile("cp.async.wait_group 1;" ::: "memory")
#define CP_WAIT0()  asm volatile("cp.async.wait_group 0;" ::: "memory")

__device__ __forceinline__ void ldm_x4(uint32_t* r, uint32_t addr) {
    asm volatile("ldmatrix.sync.aligned.m8n8.x4.shared.b16 {%0,%1,%2,%3}, [%4];"
                 : "=r"(r[0]), "=r"(r[1]), "=r"(r[2]), "=r"(r[3]) : "r"(addr));
}
__device__ __forceinline__ void mma16816(float* c, const uint32_t* a,
                                         uint32_t b0, uint32_t b1) {
    asm volatile("mma.sync.aligned.m16n8k16.row.col.f32.f16.f16.f32 "
                 "{%0,%1,%2,%3}, {%4,%5,%6,%7}, {%8,%9}, {%0,%1,%2,%3};"
                 : "+f"(c[0]), "+f"(c[1]), "+f"(c[2]), "+f"(c[3])
                 : "r"(a[0]), "r"(a[1]), "r"(a[2]), "r"(a[3]), "r"(b0), "r"(b1));
}
// fp16-accumulator variant: C/D are 2 b32 regs (4 halfs)
__device__ __forceinline__ void mma16816_h(uint32_t* c, const uint32_t* a,
                                           uint32_t b0, uint32_t b1) {
    asm volatile("mma.sync.aligned.m16n8k16.row.col.f16.f16.f16.f16 "
                 "{%0,%1}, {%2,%3,%4,%5}, {%6,%7}, {%0,%1};"
                 : "+r"(c[0]), "+r"(c[1])
                 : "r"(a[0]), "r"(a[1]), "r"(a[2]), "r"(a[3]), "r"(b0), "r"(b1));
}
__device__ __forceinline__ void ex2_h2(uint32_t& v) {
    asm("ex2.approx.f16x2 %0, %0;" : "+r"(v));
}

__device__ __forceinline__ uint32_t pack_h2(float a, float b) {
    __half2 t = __halves2half2(__float2half(a), __float2half(b));
    return *(uint32_t*)&t;
}
__device__ __forceinline__ uint32_t h2mul(uint32_t a, uint32_t b) {
    __half2 r = __hmul2(*(__half2*)&a, *(__half2*)&b);
    return *(uint32_t*)&r;
}

// ---------------- weight conversion (all four in one launch) -----------------
__global__ void conv_w_all(const float* __restrict__ wq, const float* __restrict__ wp,
                           const float* __restrict__ w1, const float* __restrict__ w2,
                           __half* __restrict__ oq, __half* __restrict__ op,
                           __half* __restrict__ o1, __half* __restrict__ o2)
{
    int i = blockIdx.x * 256 + threadIdx.x;          // 0 .. 196607
    if (i < 49152)       oq[i]          = __float2half(wq[i]);
    else if (i < 65536)  op[i - 49152]  = __float2half(wp[i - 49152]);
    else if (i < 131072) o1[i - 65536]  = __float2half(w1[i - 65536]);
    else                 o2[i - 131072] = __float2half(w2[i - 131072]);
}

// ---------------- LayerNorm -> fp16 ------------------------------------------
__global__ void __launch_bounds__(256) ln_kernel(const float* __restrict__ x,
                                                 const float* __restrict__ g,
                                                 const float* __restrict__ b,
                                                 __half* __restrict__ oh)
{
    int gtid = blockIdx.x * blockDim.x + threadIdx.x;
    int row  = gtid >> 5;
    int lane = gtid & 31;
    const float4 v = ((const float4*)(x + (size_t)row * 128))[lane];
    float s = v.x + v.y + v.z + v.w;
    #pragma unroll
    for (int o = 16; o; o >>= 1) s += __shfl_xor_sync(0xffffffffu, s, o);
    float mean = s * (1.0f / 128.0f);
    float dx = v.x - mean, dy = v.y - mean, dz = v.z - mean, dw = v.w - mean;
    float sq = dx*dx + dy*dy + dz*dz + dw*dw;
    #pragma unroll
    for (int o = 16; o; o >>= 1) sq += __shfl_xor_sync(0xffffffffu, sq, o);
    float inv = rsqrtf(sq * (1.0f / 128.0f) + 1e-5f);
    float4 gg = ((const float4*)g)[lane];
    float4 bb = ((const float4*)b)[lane];
    uint32_t* ph = (uint32_t*)(oh + (size_t)row * 128);
    ph[lane*2]     = pack_h2(dx * inv * gg.x + bb.x, dy * inv * gg.y + bb.y);
    ph[lane*2 + 1] = pack_h2(dz * inv * gg.z + bb.z, dw * inv * gg.w + bb.w);
}

// ---------------- shared GEMM pieces ------------------------------------------
#define SLAB   10240
#define STAGEB (2 * SLAB)
#define BOFF   40960
#define SOFF   71680
#define GNSMEM 73728
#define GSMEM3 (3 * STAGEB)

// load one 128-row x 32-col chunk of a [rows x K] fp16 matrix into a slab
__device__ __forceinline__ void issue_one(
    uint32_t dst, const __half* __restrict__ src,
    int rbase, int K, int k0, int tid)
{
    #pragma unroll
    for (int i = 0; i < 2; ++i) {
        int flat = tid + (i << 8);
        int row  = flat >> 2;
        int u    = flat & 3;
        cp_async16(dst + row * 80 + u * 16,
                   src + (size_t)(rbase + row) * K + k0 + u * 8);
    }
}

__device__ __forceinline__ void issue_chunk(
    uint32_t sbase, int s,
    const __half* __restrict__ A, const __half* __restrict__ B,
    int m0, int n0, int K, int k0, int tid)
{
    uint32_t st = sbase + s * STAGEB;
    issue_one(st,        A, m0, K, k0, tid);
    issue_one(st + SLAB, B, n0, K, k0, tid);
}

// ---------------- A-resident multi-N GEMM (K=128) -----------------------------
// One CTA: 128 rows x all NB 128-col blocks. A chunks resident (40KB),
// B streams through a 3-stage ring (30KB). Uniform wait_group 2.
// epi: 2 +bias,GELU (fp16), 3 plain fp16, 4 +bias+res -> y fp32 AND LN -> fp16
__global__ void __launch_bounds__(256, 2) mma_gemmN(
    const __half* __restrict__ A, const __half* __restrict__ B,
    const float* __restrict__ bias, const float* __restrict__ res,
    const float* __restrict__ gamma, const float* __restrict__ beta,
    float* __restrict__ outf, __half* __restrict__ outh,
    int N, int NB, int epi, int rev)
{
    extern __shared__ char smem[];
    const uint32_t sbase = smem_u32(smem);
    const int tid  = threadIdx.x;
    const int lane = tid & 31;
    const int wid  = tid >> 5;
    const int wm   = wid & 3;
    const int wn   = wid >> 2;
    const int mb   = rev ? (gridDim.x - 1 - (int)blockIdx.x) : (int)blockIdx.x;
    const int m0   = mb << 7;

    // prologue: A chunks 0..3 resident; B chunks 0..2 into ring
    issue_one(sbase + 0*SLAB, A, m0, 128, 0,  tid);
    issue_one(sbase + 1*SLAB, A, m0, 128, 32, tid);
    CP_COMMIT();
    issue_one(sbase + 2*SLAB, A, m0, 128, 64, tid);
    issue_one(sbase + 3*SLAB, A, m0, 128, 96, tid);
    CP_COMMIT();
    #pragma unroll
    for (int p = 0; p < 3; ++p) {
        issue_one(sbase + BOFF + p*SLAB, B, (p >> 2) << 7, 128, (p & 3) * 32, tid);
        CP_COMMIT();
    }

    float acc[2][8][4];
    #pragma unroll
    for (int i = 0; i < 2; ++i)
        #pragma unroll
        for (int j = 0; j < 8; ++j)
            #pragma unroll
            for (int k = 0; k < 4; ++k) acc[i][j][k] = 0.f;

    const int ra  = lane & 15;
    const int kha = lane >> 4;
    const int rb  = (lane & 7) + ((lane >> 4) << 3);
    const int khb = (lane >> 3) & 1;
    const int qr  = lane >> 2;
    const int ql  = lane & 3;
    const int qc  = ql * 2;
    const int NT  = NB * 4;

    int s = 0;
    for (int t = 0; t < NT; ++t) {
        CP_WAIT2();
        __syncthreads();
        const int c = t & 3;
        const uint32_t stgA = sbase + c * SLAB;
        const uint32_t stgB = sbase + BOFF + s * SLAB;
        #pragma unroll
        for (int kk = 0; kk < 2; ++kk) {
            uint32_t ah[2][4], bf[4][4];
            #pragma unroll
            for (int mi = 0; mi < 2; ++mi) {
                uint32_t addr = stgA + (wm*32 + mi*16 + ra) * 80 + kk*32 + kha*16;
                ldm_x4(ah[mi], addr);
            }
            #pragma unroll
            for (int g = 0; g < 4; ++g) {
                uint32_t addr = stgB + (wn*64 + g*16 + rb) * 80 + kk*32 + khb*16;
                ldm_x4(bf[g], addr);
            }
            #pragma unroll
            for (int mi = 0; mi < 2; ++mi)
                #pragma unroll
                for (int g = 0; g < 4; ++g) {
                    mma16816(acc[mi][2*g],   ah[mi], bf[g][0], bf[g][1]);
                    mma16816(acc[mi][2*g+1], ah[mi], bf[g][2], bf[g][3]);
                }
        }
        __syncthreads();
        if (t + 3 < NT)
            issue_one(sbase + BOFF + s*SLAB, B, ((t+3) >> 2) << 7, 128,
                      ((t+3) & 3) * 32, tid);
        CP_COMMIT();
        s = (s == 2) ? 0 : s + 1;

        if (c == 3) {
            const int nb    = t >> 2;
            const int mbase = m0 + wm * 32;
            const int nbase = (nb << 7) + wn * 64;

            if (epi == 4) {
                float* stats = (float*)(smem + SOFF);
                __syncthreads();
                #pragma unroll
                for (int mi = 0; mi < 2; ++mi)
                    #pragma unroll
                    for (int half = 0; half < 2; ++half) {
                        const int r = mbase + mi*16 + half*8 + qr;
                        float rs = 0.f, rq = 0.f;
                        #pragma unroll
                        for (int ni = 0; ni < 8; ++ni) {
                            const int cc2 = nbase + ni*8 + qc;
                            float v0 = acc[mi][ni][half*2]   + bias[cc2];
                            float v1 = acc[mi][ni][half*2+1] + bias[cc2+1];
                            size_t base = (size_t)r * N + cc2;
                            float2 rr = *(const float2*)(res + base);
                            v0 += rr.x; v1 += rr.y;
                            acc[mi][ni][half*2]   = v0;
                            acc[mi][ni][half*2+1] = v1;
                            *(float2*)(outf + base) = make_float2(v0, v1);
                            rs += v0 + v1;
                            rq += v0*v0 + v1*v1;
                        }
                        rs += __shfl_xor_sync(0xffffffffu, rs, 1);
                        rq += __shfl_xor_sync(0xffffffffu, rq, 1);
                        rs += __shfl_xor_sync(0xffffffffu, rs, 2);
                        rq += __shfl_xor_sync(0xffffffffu, rq, 2);
                        if (ql == 0) {
                            int rl = wm*32 + mi*16 + half*8 + qr;
                            stats[rl*4 + wn*2]     = rs;
                            stats[rl*4 + wn*2 + 1] = rq;
                        }
                    }
                __syncthreads();
                #pragma unroll
                for (int mi = 0; mi < 2; ++mi)
                    #pragma unroll
                    for (int half = 0; half < 2; ++half) {
                        const int r  = mbase + mi*16 + half*8 + qr;
                        const int rl = wm*32 + mi*16 + half*8 + qr;
                        float sm2 = stats[rl*4] + stats[rl*4 + 2];
                        float q2  = stats[rl*4 + 1] + stats[rl*4 + 3];
                        float mean = sm2 * (1.0f / 128.0f);
                        float inv  = rsqrtf(q2 * (1.0f / 128.0f) - mean*mean + 1e-5f);
                        #pragma unroll
                        for (int ni = 0; ni < 8; ++ni) {
                            const int cc2 = nbase + ni*8 + qc;
                            float l0 = (acc[mi][ni][half*2]   - mean) * inv * gamma[cc2]   + beta[cc2];
                            float l1 = (acc[mi][ni][half*2+1] - mean) * inv * gamma[cc2+1] + beta[cc2+1];
                            *(uint32_t*)(outh + (size_t)r * N + cc2) = pack_h2(l0, l1);
                        }
                    }
            } else {
                #pragma unroll
                for (int mi = 0; mi < 2; ++mi)
                    #pragma unroll
                    for (int half = 0; half < 2; ++half) {
                        const int r = mbase + mi * 16 + half * 8 + qr;
                        #pragma unroll
                        for (int ni = 0; ni < 8; ++ni) {
                            const int cc2 = nbase + ni * 8 + qc;
                            float v0 = acc[mi][ni][half * 2];
                            float v1 = acc[mi][ni][half * 2 + 1];
                            if (epi == 2) {
                                v0 += bias[cc2]; v1 += bias[cc2 + 1];
                                v0 = 0.5f * v0 * (1.0f + erff(v0 * 0.70710678118654752f));
                                v1 = 0.5f * v1 * (1.0f + erff(v1 * 0.70710678118654752f));
                            }
                            *(uint32_t*)(outh + (size_t)r * N + cc2) = pack_h2(v0, v1);
                        }
                    }
            }
            if (t + 1 < NT) {
                #pragma unroll
                for (int i = 0; i < 2; ++i)
                    #pragma unroll
                    for (int j = 0; j < 8; ++j)
                        #pragma unroll
                        for (int k = 0; k < 4; ++k) acc[i][j][k] = 0.f;
            }
        }
    }
}

// ---------------- pipelined GEMM (K=512, fc2), 3-stage ------------------------
__global__ void __launch_bounds__(256, 2) mma_gemm(
    const __half* __restrict__ A, const __half* __restrict__ B,
    const float* __restrict__ bias, const float* __restrict__ res,
    float* __restrict__ outf, int N, int K)
{
    extern __shared__ char smem[];
    const uint32_t sbase = smem_u32(smem);
    const int tid  = threadIdx.x;
    const int lane = tid & 31;
    const int wid  = tid >> 5;
    const int wm   = wid & 3;
    const int wn   = wid >> 2;
    const int m0 = blockIdx.y << 7;
    const int n0 = blockIdx.x << 7;
    const int NC = K >> 5;

    float acc[2][8][4];
    #pragma unroll
    for (int i = 0; i < 2; ++i)
        #pragma unroll
        for (int j = 0; j < 8; ++j)
            #pragma unroll
            for (int k = 0; k < 4; ++k) acc[i][j][k] = 0.f;

    issue_chunk(sbase, 0, A, B, m0, n0, K, 0, tid);  CP_COMMIT();
    issue_chunk(sbase, 1, A, B, m0, n0, K, 32, tid); CP_COMMIT();
    issue_chunk(sbase, 2, A, B, m0, n0, K, 64, tid); CP_COMMIT();

    const int ra  = lane & 15;
    const int kha = lane >> 4;
    const int rb  = (lane & 7) + ((lane >> 4) << 3);
    const int khb = (lane >> 3) & 1;

    int s = 0;
    for (int c = 0; c < NC; ++c) {
        CP_WAIT2();
        __syncthreads();

        const uint32_t stg = sbase + s * STAGEB;
        #pragma unroll
        for (int kk = 0; kk < 2; ++kk) {
            uint32_t ah[2][4], bf[4][4];
            #pragma unroll
            for (int mi = 0; mi < 2; ++mi) {
                uint32_t addr = stg + (wm*32 + mi*16 + ra) * 80 + kk*32 + kha*16;
                ldm_x4(ah[mi], addr);
            }
            #pragma unroll
            for (int g = 0; g < 4; ++g) {
                uint32_t addr = stg + SLAB + (wn*64 + g*16 + rb) * 80 + kk*32 + khb*16;
                ldm_x4(bf[g], addr);
            }
            #pragma unroll
            for (int mi = 0; mi < 2; ++mi)
                #pragma unroll
                for (int g = 0; g < 4; ++g) {
                    mma16816(acc[mi][2*g],   ah[mi], bf[g][0], bf[g][1]);
                    mma16816(acc[mi][2*g+1], ah[mi], bf[g][2], bf[g][3]);
                }
        }
        __syncthreads();
        if (c + 3 < NC)
            issue_chunk(sbase, s, A, B, m0, n0, K, (c + 3) << 5, tid);
        CP_COMMIT();
        s = (s == 2) ? 0 : s + 1;
    }

    const int mbase = m0 + wm * 32;
    const int nbase = n0 + wn * 64;
    const int qr = lane >> 2;
    const int qc = (lane & 3) * 2;
    #pragma unroll
    for (int mi = 0; mi < 2; ++mi) {
        #pragma unroll
        for (int half = 0; half < 2; ++half) {
            const int r = mbase + mi * 16 + half * 8 + qr;
            #pragma unroll
            for (int ni = 0; ni < 8; ++ni) {
                const int cc = nbase + ni * 8 + qc;
                float v0 = acc[mi][ni][half * 2] + bias[cc];
                float v1 = acc[mi][ni][half * 2 + 1] + bias[cc + 1];
                size_t base = (size_t)r * N + cc;
                float2 rr = *(const float2*)(res + base);
                v0 += rr.x; v1 += rr.y;
                *(float2*)(outf + base) = make_float2(v0, v1);
            }
        }
    }
}

// ---------------- MMA CSWin attention (ex2.f16x2, constant-fragment lsum) ----
#define A_SK   0
#define A_VT   20480
#define A_VN   37376
#define A_CWS  57856
#define A_CB   59008
#define ASMEM  59136

__device__ __forceinline__ int lmap(int s, int br, int widx) {
    return br == 0 ? (((s >> 1) << 7) + (widx << 1) + (s & 1))
                   : ((((widx << 1) + (s >> 7)) << 7) + (s & 127));
}

__global__ void __launch_bounds__(256, 2) attn_mma(
    const __half* __restrict__ qkv,
    const float* __restrict__ cw0, const float* __restrict__ cb0,
    const float* __restrict__ cw1, const float* __restrict__ cb1,
    __half* __restrict__ att)
{
    extern __shared__ char smem[];
    const uint32_t sb = smem_u32(smem);
    const int tid  = threadIdx.x;
    const int lane = tid & 31;
    const int w    = tid >> 5;
    const int win  = blockIdx.x;
    const int head = blockIdx.y;
    const int br   = blockIdx.z;
    const int b    = win >> 6;
    const int widx = win & 63;
    const int cbase = br * 64 + head * 32;

    // ---- phase 1: stage Q, build (scale*log2e)-folded A-fragments -----------
    #pragma unroll
    for (int i = 0; i < 4; ++i) {
        int flat = tid + (i << 8);
        int s = flat >> 2, part = flat & 3;
        size_t grow = (size_t)(b * 16384 + lmap(s, br, widx)) * 384 + cbase + part * 8;
        cp_async16(sb + A_SK + s * 80 + part * 16, qkv + grow);
    }
    CP_COMMIT(); CP_WAIT0();
    __syncthreads();

    const int ra  = lane & 15;
    const int kha = lane >> 4;
    const float scl = 0.17677669529663687f * 1.4426950408889634f;
    const __half2 sch = __floats2half2_rn(scl, scl);
    const uint32_t scu = *(const uint32_t*)&sch;
    uint32_t aq[2][2][4];
    #pragma unroll
    for (int mi = 0; mi < 2; ++mi)
        #pragma unroll
        for (int kk = 0; kk < 2; ++kk) {
            uint32_t addr = sb + A_SK + (w*32 + mi*16 + ra) * 80 + kk*32 + kha*16;
            ldm_x4(aq[mi][kk], addr);
            #pragma unroll
            for (int j = 0; j < 4; ++j) aq[mi][kk][j] = h2mul(aq[mi][kk][j], scu);
        }
    __syncthreads();

    // ---- phase 2: load K, V (transposed + normal), conv weights -------------
    #pragma unroll
    for (int i = 0; i < 4; ++i) {
        int flat = tid + (i << 8);
        int s = flat >> 2, part = flat & 3;
        size_t grow = (size_t)(b * 16384 + lmap(s, br, widx)) * 384 + cbase + 128 + part * 8;
        cp_async16(sb + A_SK + s * 80 + part * 16, qkv + grow);
    }
    CP_COMMIT();
    {
        const int s = tid;
        size_t grow = (size_t)(b * 16384 + lmap(s, br, widx)) * 384 + cbase + 256;
        __half vh[32];
        #pragma unroll
        for (int u = 0; u < 4; ++u)
            *(uint4*)&vh[u*8] = *(const uint4*)(qkv + grow + u*8);
        __half* th = (__half*)(smem + A_VT);
        #pragma unroll
        for (int d = 0; d < 32; ++d)
            th[d * 264 + s] = vh[d];
        #pragma unroll
        for (int u = 0; u < 4; ++u)
            *(uint4*)(smem + A_VN + s * 80 + u * 16) = *(uint4*)&vh[u*8];
    }
    {
        const float* cw = br ? cw1 : cw0;
        const float* cb = br ? cb1 : cb0;
        float* cws = (float*)(smem + A_CWS);
        float* cbs = (float*)(smem + A_CB);
        for (int i = tid; i < 288; i += 256) {
            int d = i / 9, tap = i % 9;
            cws[tap * 32 + d] = cw[head * 288 + i];
        }
        if (tid < 32) cbs[tid] = cb[head * 32 + tid];
    }
    CP_WAIT0();
    __syncthreads();

    // ---- flash loop: joint-mi S (fp16 acc), ex2.f16x2, const-fragment lsum --
    const int rb  = (lane & 7) + ((lane >> 4) << 3);
    const int khb = (lane >> 3) & 1;
    const uint32_t vones = (lane < 4) ? 0x3C003C00u : 0u;

    float oacc[2][4][4];
    float lsacc[2][4];
    #pragma unroll
    for (int i = 0; i < 2; ++i) {
        #pragma unroll
        for (int j = 0; j < 4; ++j) {
            lsacc[i][j] = 0.f;
            #pragma unroll
            for (int k = 0; k < 4; ++k) oacc[i][j][k] = 0.f;
        }
    }

    for (int cc = 0; cc < 4; ++cc) {
        uint32_t sacc_h[2][8][2];
        #pragma unroll
        for (int mi = 0; mi < 2; ++mi)
            #pragma unroll
            for (int j = 0; j < 8; ++j) { sacc_h[mi][j][0] = 0u; sacc_h[mi][j][1] = 0u; }

        #pragma unroll
        for (int kk = 0; kk < 2; ++kk) {
            uint32_t bh[4][4];
            #pragma unroll
            for (int g = 0; g < 4; ++g) {
                uint32_t addr = sb + A_SK + (cc*64 + g*16 + rb) * 80 + kk*32 + khb*16;
                ldm_x4(bh[g], addr);
            }
            #pragma unroll
            for (int mi = 0; mi < 2; ++mi)
                #pragma unroll
                for (int g = 0; g < 4; ++g) {
                    mma16816_h(sacc_h[mi][2*g],   aq[mi][kk], bh[g][0], bh[g][1]);
                    mma16816_h(sacc_h[mi][2*g+1], aq[mi][kk], bh[g][2], bh[g][3]);
                }
        }

        #pragma unroll
        for (int mi = 0; mi < 2; ++mi)
            #pragma unroll
            for (int nt = 0; nt < 8; ++nt) {
                ex2_h2(sacc_h[mi][nt][0]);
                ex2_h2(sacc_h[mi][nt][1]);
            }

        #pragma unroll
        for (int kt = 0; kt < 4; ++kt) {
            uint32_t vb[2][4];
            #pragma unroll
            for (int g = 0; g < 2; ++g) {
                uint32_t addr = sb + A_VT + (g*16 + rb) * 528 + (cc*64 + kt*16) * 2 + khb*16;
                ldm_x4(vb[g], addr);
            }
            #pragma unroll
            for (int mi = 0; mi < 2; ++mi) {
                uint32_t pa[4] = { sacc_h[mi][2*kt][0],   sacc_h[mi][2*kt][1],
                                   sacc_h[mi][2*kt+1][0], sacc_h[mi][2*kt+1][1] };
                #pragma unroll
                for (int g = 0; g < 2; ++g) {
                    mma16816(oacc[mi][2*g],   pa, vb[g][0], vb[g][1]);
                    mma16816(oacc[mi][2*g+1], pa, vb[g][2], vb[g][3]);
                }
                mma16816(lsacc[mi], pa, vones, vones);
            }
        }
    }

    // ---- finalize: 1/lsum, bias, LePE, scatter store -------------------------
    const int qr = lane >> 2;
    const int qc = (lane & 3) * 2;
    float ls[4];
    #pragma unroll
    for (int mi = 0; mi < 2; ++mi)
        #pragma unroll
        for (int rh = 0; rh < 2; ++rh) {
            float v = __shfl_sync(0xffffffffu, lsacc[mi][rh*2], lane & ~3);
            ls[mi*2 + rh] = 1.0f / v;
        }

    const float* cws = (const float*)(smem + A_CWS);
    const float* cbs = (const float*)(smem + A_CB);
    const int Ws = (br == 0) ? 2 : 128;
    const int Hs = (br == 0) ? 128 : 2;

    #pragma unroll
    for (int mi = 0; mi < 2; ++mi)
        #pragma unroll
        for (int rh = 0; rh < 2; ++rh) {
            const int r  = mi*2 + rh;
            const int tl = w*32 + mi*16 + rh*8 + qr;
            const int yy = (br == 0) ? (tl >> 1) : (tl >> 7);
            const int xx = tl & (Ws - 1);
            const int lq = lmap(tl, br, widx);
            const size_t ob = ((size_t)(b * 16384 + lq)) * 128 + cbase;
            #pragma unroll
            for (int nt = 0; nt < 4; ++nt) {
                const int d0 = nt*8 + qc;
                float v0 = oacc[mi][nt][rh*2]   * ls[r] + cbs[d0];
                float v1 = oacc[mi][nt][rh*2+1] * ls[r] + cbs[d0+1];
                #pragma unroll
                for (int dy = -1; dy <= 1; ++dy) {
                    int ny = yy + dy;
                    if (ny < 0 || ny >= Hs) continue;
                    #pragma unroll
                    for (int dx = -1; dx <= 1; ++dx) {
                        int nx = xx + dx;
                        if (nx < 0 || nx >= Ws) continue;
                        int tp  = ny * Ws + nx;
                        int tap = (dy + 1) * 3 + (dx + 1);
                        float2 ww = *(const float2*)&cws[tap*32 + d0];
                        __half2 hv = *(const __half2*)(smem + A_VN + tp*80 + d0*2);
                        float2 vv = __half22float2(hv);
                        v0 += ww.x * vv.x;
                        v1 += ww.y * vv.y;
                    }
                }
                *(uint32_t*)(att + ob + d0) = pack_h2(v0, v1);
            }
        }
}

// ---------------- launch ----------------------------------------------------
extern "C" void kernel_launch(void* const* d_in, const int* in_sizes, int n_in,
                              void* d_out, int out_size)
{
    const float* x      = (const float*)d_in[0];
    const float* ln1_g  = (const float*)d_in[1];
    const float* ln1_b  = (const float*)d_in[2];
    const float* w_qkv  = (const float*)d_in[3];
    const float* w_proj = (const float*)d_in[4];
    const float* b_proj = (const float*)d_in[5];
    const float* cw0    = (const float*)d_in[6];
    const float* cb0    = (const float*)d_in[7];
    const float* cw1    = (const float*)d_in[8];
    const float* cb1    = (const float*)d_in[9];
    const float* ln2_g  = (const float*)d_in[10];
    const float* ln2_b  = (const float*)d_in[11];
    const float* w1     = (const float*)d_in[12];
    const float* b1     = (const float*)d_in[13];
    const float* w2     = (const float*)d_in[14];
    const float* b2     = (const float*)d_in[15];
    float* out = (float*)d_out;

    __half *ln, *qkv, *att, *ln2, *h, *wq_h, *wp_h, *w1_h, *w2_h;
    float *y;
    cudaGetSymbolAddress((void**)&ln,   g_ln);
    cudaGetSymbolAddress((void**)&qkv,  g_qkv);
    cudaGetSymbolAddress((void**)&att,  g_att);
    cudaGetSymbolAddress((void**)&y,    g_y);
    cudaGetSymbolAddress((void**)&ln2,  g_ln2);
    cudaGetSymbolAddress((void**)&h,    g_h);
    cudaGetSymbolAddress((void**)&wq_h, g_wq_h);
    cudaGetSymbolAddress((void**)&wp_h, g_wp_h);
    cudaGetSymbolAddress((void**)&w1_h, g_w1_h);
    cudaGetSymbolAddress((void**)&w2_h, g_w2_h);

    cudaFuncSetAttribute(mma_gemmN, cudaFuncAttributeMaxDynamicSharedMemorySize, GNSMEM);
    cudaFuncSetAttribute(mma_gemm,  cudaFuncAttributeMaxDynamicSharedMemorySize, GSMEM3);
    cudaFuncSetAttribute(attn_mma,  cudaFuncAttributeMaxDynamicSharedMemorySize, ASMEM);

    // 0) weight conversion (single tiny launch)
    conv_w_all<<<768, 256>>>(w_qkv, w_proj, w1, w2, wq_h, wp_h, w1_h, w2_h);

    // 1) LN1 -> fp16 (writes ln ascending)
    ln_kernel<<<16384, 256>>>(x, ln1_g, ln1_b, ln);
    // 2) QKV -> fp16 (A-resident over NB=3, REVERSED m-order)
    mma_gemmN<<<1024, 256, GNSMEM>>>(ln, wq_h, nullptr, nullptr,
                                     nullptr, nullptr, nullptr, qkv,
                                     384, 3, 3, 1);
    // 3) MMA attention + LePE -> fp16
    attn_mma<<<dim3(512, 2, 2), 256, ASMEM>>>(qkv, cw0, cb0, cw1, cb1, att);
    // 4) proj + bias + residual(x) -> y fp32 AND fused LN2 -> fp16 (ascending)
    mma_gemmN<<<1024, 256, GNSMEM>>>(att, wp_h, b_proj, x,
                                     ln2_g, ln2_b, y, ln2,
                                     128, 1, 4, 0);
    // 5) fc1 + bias + GELU -> fp16 (A-resident over NB=4, REVERSED m-order)
    mma_gemmN<<<1024, 256, GNSMEM>>>(ln2, w1_h, b1, nullptr,
                                     nullptr, nullptr, nullptr, h,
                                     512, 4, 2, 1);
    // 6) fc2 + bias + residual(y) -> out (ascending, 3-stage pipelined K=512)
    mma_gemm<<<dim3(1, 1024), 256, GSMEM3>>>(h, w2_h, b2, y, out, 128, 512);
}

// round 17
// speedup vs baseline: 1.0294x; 1.0294x over previous
#include <cuda_runtime.h>
#include <cuda_fp16.h>
#include <math.h>
#include <stdint.h>

// Shapes: B=8, H=W=128 -> LT = 131072 rows, C = 128
#define LT 131072

// ---------------- scratch (static device arrays; no allocation) -------------
__device__ __half g_ln [(size_t)LT * 128];
__device__ __half g_qkv[(size_t)LT * 384];
__device__ __half g_att[(size_t)LT * 128];
__device__ __half g_y  [(size_t)LT * 128];
__device__ __half g_ln2[(size_t)LT * 128];
__device__ __half g_h  [(size_t)LT * 512];
__device__ __half g_wq_h[384 * 128];
__device__ __half g_wp_h[128 * 128];
__device__ __half g_w1_h[512 * 128];
__device__ __half g_w2_h[128 * 512];

// ---------------- PTX helpers (sm_80-compatible only) ------------------------
__device__ __forceinline__ uint32_t smem_u32(const void* p) {
    uint32_t a;
    asm("{ .reg .u64 t; cvta.to.shared.u64 t, %1; cvt.u32.u64 %0, t; }" : "=r"(a) : "l"(p));
    return a;
}
__device__ __forceinline__ void cp_async16(uint32_t saddr, const void* gaddr) {
    asm volatile("cp.async.cg.shared.global [%0], [%1], 16;"
                 :: "r"(saddr), "l"(gaddr) : "memory");
}
#define CP_COMMIT() asm volatile("cp.async.commit_group;" ::: "memory")
#define CP_WAIT2()  asm volatile("cp.async.wait_group 2;" ::: "memory")
#define CP_WAIT1()  asm volatile("cp.async.wait_group 1;" ::: "memory")
#define CP_WAIT0()  asm volatile("cp.async.wait_group 0;" ::: "memory")

__device__ __forceinline__ void ldm_x4(uint32_t* r, uint32_t addr) {
    asm volatile("ldmatrix.sync.aligned.m8n8.x4.shared.b16 {%0,%1,%2,%3}, [%4];"
                 : "=r"(r[0]), "=r"(r[1]), "=r"(r[2]), "=r"(r[3]) : "r"(addr));
}
__device__ __forceinline__ void mma16816(float* c, const uint32_t* a,
                                         uint32_t b0, uint32_t b1) {
    asm volatile("mma.sync.aligned.m16n8k16.row.col.f32.f16.f16.f32 "
                 "{%0,%1,%2,%3}, {%4,%5,%6,%7}, {%8,%9}, {%0,%1,%2,%3};"
                 : "+f"(c[0]), "+f"(c[1]), "+f"(c[2]), "+f"(c[3])
                 : "r"(a[0]), "r"(a[1]), "r"(a[2]), "r"(a[3]), "r"(b0), "r"(b1));
}
// fp16-accumulator variant: C/D are 2 b32 regs (4 halfs)
__device__ __forceinline__ void mma16816_h(uint32_t* c, const uint32_t* a,
                                           uint32_t b0, uint32_t b1) {
    asm volatile("mma.sync.aligned.m16n8k16.row.col.f16.f16.f16.f16 "
                 "{%0,%1}, {%2,%3,%4,%5}, {%6,%7}, {%0,%1};"
                 : "+r"(c[0]), "+r"(c[1])
                 : "r"(a[0]), "r"(a[1]), "r"(a[2]), "r"(a[3]), "r"(b0), "r"(b1));
}
__device__ __forceinline__ void ex2_h2(uint32_t& v) {
    asm("ex2.approx.f16x2 %0, %0;" : "+r"(v));
}

__device__ __forceinline__ uint32_t pack_h2(float a, float b) {
    __half2 t = __halves2half2(__float2half(a), __float2half(b));
    return *(uint32_t*)&t;
}
__device__ __forceinline__ uint32_t h2mul(uint32_t a, uint32_t b) {
    __half2 r = __hmul2(*(__half2*)&a, *(__half2*)&b);
    return *(uint32_t*)&r;
}

// ---------------- fused LN1 + weight conversion -------------------------------
__global__ void __launch_bounds__(256) ln_conv_kernel(
    const float* __restrict__ x, const float* __restrict__ g,
    const float* __restrict__ b, __half* __restrict__ oh,
    const float* __restrict__ wq, const float* __restrict__ wp,
    const float* __restrict__ w1, const float* __restrict__ w2,
    __half* __restrict__ oq, __half* __restrict__ op,
    __half* __restrict__ o1, __half* __restrict__ o2)
{
    if (blockIdx.x >= 16384) {
        int i = (blockIdx.x - 16384) * 256 + threadIdx.x;   // 0 .. 196607
        if (i < 49152)       oq[i]          = __float2half(wq[i]);
        else if (i < 65536)  op[i - 49152]  = __float2half(wp[i - 49152]);
        else if (i < 131072) o1[i - 65536]  = __float2half(w1[i - 65536]);
        else                 o2[i - 131072] = __float2half(w2[i - 131072]);
        return;
    }
    int gtid = blockIdx.x * blockDim.x + threadIdx.x;
    int row  = gtid >> 5;
    int lane = gtid & 31;
    const float4 v = ((const float4*)(x + (size_t)row * 128))[lane];
    float s = v.x + v.y + v.z + v.w;
    #pragma unroll
    for (int o = 16; o; o >>= 1) s += __shfl_xor_sync(0xffffffffu, s, o);
    float mean = s * (1.0f / 128.0f);
    float dx = v.x - mean, dy = v.y - mean, dz = v.z - mean, dw = v.w - mean;
    float sq = dx*dx + dy*dy + dz*dz + dw*dw;
    #pragma unroll
    for (int o = 16; o; o >>= 1) sq += __shfl_xor_sync(0xffffffffu, sq, o);
    float inv = rsqrtf(sq * (1.0f / 128.0f) + 1e-5f);
    float4 gg = ((const float4*)g)[lane];
    float4 bb = ((const float4*)b)[lane];
    uint32_t* ph = (uint32_t*)(oh + (size_t)row * 128);
    ph[lane*2]     = pack_h2(dx * inv * gg.x + bb.x, dy * inv * gg.y + bb.y);
    ph[lane*2 + 1] = pack_h2(dz * inv * gg.z + bb.z, dw * inv * gg.w + bb.w);
}

// ---------------- shared GEMM pieces ------------------------------------------
#define SLAB   10240
#define STAGEB (2 * SLAB)
#define G128SMEM (4 * STAGEB)
#define GSMEM3   (3 * STAGEB)

__device__ __forceinline__ void issue_chunk(
    uint32_t sbase, int s,
    const __half* __restrict__ A, const __half* __restrict__ B,
    int m0, int n0, int K, int k0, int tid)
{
    uint32_t st = sbase + s * STAGEB;
    const __half* srcs[2] = { A, B };
    #pragma unroll
    for (int a = 0; a < 2; ++a) {
        const __half* src = srcs[a];
        const int rbase = (a == 0) ? m0 : n0;
        #pragma unroll
        for (int i = 0; i < 2; ++i) {
            int flat = tid + (i << 8);
            int row  = flat >> 2;
            int u    = flat & 3;
            const void* g = src + (size_t)(rbase + row) * K + k0 + u * 8;
            cp_async16(st + a * SLAB + row * 80 + u * 16, g);
        }
    }
}

// ---------------- single-shot K=128 GEMM (staged waits, optional reverse-m) ---
// epi: 2 +bias,GELU (fp16), 3 plain fp16, 4 +bias+res -> y fp16 AND LayerNorm -> fp16
__global__ void __launch_bounds__(256, 2) mma_gemm128(
    const __half* __restrict__ A, const __half* __restrict__ B,
    const float* __restrict__ bias, const float* __restrict__ res,
    const float* __restrict__ gamma, const float* __restrict__ beta,
    __half* __restrict__ outy, __half* __restrict__ outh,
    int N, int epi, int rev)
{
    extern __shared__ char smem[];
    const uint32_t sbase = smem_u32(smem);
    const int tid  = threadIdx.x;
    const int lane = tid & 31;
    const int wid  = tid >> 5;
    const int wm   = wid & 3;
    const int wn   = wid >> 2;
    const int mb   = rev ? (gridDim.y - 1 - blockIdx.y) : blockIdx.y;
    const int m0 = mb << 7;
    const int n0 = blockIdx.x << 7;

    issue_chunk(sbase, 0, A, B, m0, n0, 128, 0,  tid);
    issue_chunk(sbase, 1, A, B, m0, n0, 128, 32, tid);
    CP_COMMIT();
    issue_chunk(sbase, 2, A, B, m0, n0, 128, 64, tid);
    issue_chunk(sbase, 3, A, B, m0, n0, 128, 96, tid);
    CP_COMMIT();

    float acc[2][8][4];
    #pragma unroll
    for (int i = 0; i < 2; ++i)
        #pragma unroll
        for (int j = 0; j < 8; ++j)
            #pragma unroll
            for (int k = 0; k < 4; ++k) acc[i][j][k] = 0.f;

    const int ra  = lane & 15;
    const int kha = lane >> 4;
    const int rb  = (lane & 7) + ((lane >> 4) << 3);
    const int khb = (lane >> 3) & 1;

    CP_WAIT1();
    __syncthreads();

    #pragma unroll
    for (int c = 0; c < 4; ++c) {
        if (c == 2) {
            CP_WAIT0();
            __syncthreads();
        }
        const uint32_t stg = sbase + c * STAGEB;
        #pragma unroll
        for (int kk = 0; kk < 2; ++kk) {
            uint32_t ah[2][4], bf[4][4];
            #pragma unroll
            for (int mi = 0; mi < 2; ++mi) {
                uint32_t addr = stg + (wm*32 + mi*16 + ra) * 80 + kk*32 + kha*16;
                ldm_x4(ah[mi], addr);
            }
            #pragma unroll
            for (int g = 0; g < 4; ++g) {
                uint32_t addr = stg + SLAB + (wn*64 + g*16 + rb) * 80 + kk*32 + khb*16;
                ldm_x4(bf[g], addr);
            }
            #pragma unroll
            for (int mi = 0; mi < 2; ++mi)
                #pragma unroll
                for (int g = 0; g < 4; ++g) {
                    mma16816(acc[mi][2*g],   ah[mi], bf[g][0], bf[g][1]);
                    mma16816(acc[mi][2*g+1], ah[mi], bf[g][2], bf[g][3]);
                }
        }
    }

    const int mbase = m0 + wm * 32;
    const int nbase = n0 + wn * 64;
    const int qr = lane >> 2;
    const int ql = lane & 3;
    const int qc = ql * 2;

    if (epi == 4) {
        float* stats = (float*)smem;
        __syncthreads();
        #pragma unroll
        for (int mi = 0; mi < 2; ++mi)
            #pragma unroll
            for (int half = 0; half < 2; ++half) {
                const int r = mbase + mi*16 + half*8 + qr;
                float rs = 0.f, rq = 0.f;
                #pragma unroll
                for (int ni = 0; ni < 8; ++ni) {
                    const int cc = nbase + ni*8 + qc;
                    float v0 = acc[mi][ni][half*2]   + bias[cc];
                    float v1 = acc[mi][ni][half*2+1] + bias[cc+1];
                    size_t base = (size_t)r * N + cc;
                    float2 rr = *(const float2*)(res + base);
                    v0 += rr.x; v1 += rr.y;
                    acc[mi][ni][half*2]   = v0;
                    acc[mi][ni][half*2+1] = v1;
                    *(uint32_t*)(outy + base) = pack_h2(v0, v1);
                    rs += v0 + v1;
                    rq += v0*v0 + v1*v1;
                }
                rs += __shfl_xor_sync(0xffffffffu, rs, 1);
                rq += __shfl_xor_sync(0xffffffffu, rq, 1);
                rs += __shfl_xor_sync(0xffffffffu, rs, 2);
                rq += __shfl_xor_sync(0xffffffffu, rq, 2);
                if (ql == 0) {
                    int rl = wm*32 + mi*16 + half*8 + qr;
                    stats[rl*4 + wn*2]     = rs;
                    stats[rl*4 + wn*2 + 1] = rq;
                }
            }
        __syncthreads();
        #pragma unroll
        for (int mi = 0; mi < 2; ++mi)
            #pragma unroll
            for (int half = 0; half < 2; ++half) {
                const int r  = mbase + mi*16 + half*8 + qr;
                const int rl = wm*32 + mi*16 + half*8 + qr;
                float s = stats[rl*4] + stats[rl*4 + 2];
                float q = stats[rl*4 + 1] + stats[rl*4 + 3];
                float mean = s * (1.0f / 128.0f);
                float inv  = rsqrtf(q * (1.0f / 128.0f) - mean*mean + 1e-5f);
                #pragma unroll
                for (int ni = 0; ni < 8; ++ni) {
                    const int cc = nbase + ni*8 + qc;
                    float l0 = (acc[mi][ni][half*2]   - mean) * inv * gamma[cc]   + beta[cc];
                    float l1 = (acc[mi][ni][half*2+1] - mean) * inv * gamma[cc+1] + beta[cc+1];
                    *(uint32_t*)(outh + (size_t)r * N + cc) = pack_h2(l0, l1);
                }
            }
        return;
    }

    #pragma unroll
    for (int mi = 0; mi < 2; ++mi) {
        #pragma unroll
        for (int half = 0; half < 2; ++half) {
            const int r = mbase + mi * 16 + half * 8 + qr;
            #pragma unroll
            for (int ni = 0; ni < 8; ++ni) {
                const int cc = nbase + ni * 8 + qc;
                float v0 = acc[mi][ni][half * 2];
                float v1 = acc[mi][ni][half * 2 + 1];
                if (epi == 2) {
                    v0 += bias[cc]; v1 += bias[cc + 1];
                    v0 = 0.5f * v0 * (1.0f + erff(v0 * 0.70710678118654752f));
                    v1 = 0.5f * v1 * (1.0f + erff(v1 * 0.70710678118654752f));
                }
                *(uint32_t*)(outh + (size_t)r * N + cc) = pack_h2(v0, v1);
            }
        }
    }
}

// ---------------- pipelined GEMM (K=512, fc2), 3-stage, fp16 residual ---------
__global__ void __launch_bounds__(256, 2) mma_gemm(
    const __half* __restrict__ A, const __half* __restrict__ B,
    const float* __restrict__ bias, const __half* __restrict__ res,
    float* __restrict__ outf, int N, int K)
{
    extern __shared__ char smem[];
    const uint32_t sbase = smem_u32(smem);
    const int tid  = threadIdx.x;
    const int lane = tid & 31;
    const int wid  = tid >> 5;
    const int wm   = wid & 3;
    const int wn   = wid >> 2;
    const int m0 = blockIdx.y << 7;
    const int n0 = blockIdx.x << 7;
    const int NC = K >> 5;

    float acc[2][8][4];
    #pragma unroll
    for (int i = 0; i < 2; ++i)
        #pragma unroll
        for (int j = 0; j < 8; ++j)
            #pragma unroll
            for (int k = 0; k < 4; ++k) acc[i][j][k] = 0.f;

    issue_chunk(sbase, 0, A, B, m0, n0, K, 0, tid);  CP_COMMIT();
    issue_chunk(sbase, 1, A, B, m0, n0, K, 32, tid); CP_COMMIT();
    issue_chunk(sbase, 2, A, B, m0, n0, K, 64, tid); CP_COMMIT();

    const int ra  = lane & 15;
    const int kha = lane >> 4;
    const int rb  = (lane & 7) + ((lane >> 4) << 3);
    const int khb = (lane >> 3) & 1;

    int s = 0;
    for (int c = 0; c < NC; ++c) {
        CP_WAIT2();
        __syncthreads();

        const uint32_t stg = sbase + s * STAGEB;
        #pragma unroll
        for (int kk = 0; kk < 2; ++kk) {
            uint32_t ah[2][4], bf[4][4];
            #pragma unroll
            for (int mi = 0; mi < 2; ++mi) {
                uint32_t addr = stg + (wm*32 + mi*16 + ra) * 80 + kk*32 + kha*16;
                ldm_x4(ah[mi], addr);
            }
            #pragma unroll
            for (int g = 0; g < 4; ++g) {
                uint32_t addr = stg + SLAB + (wn*64 + g*16 + rb) * 80 + kk*32 + khb*16;
                ldm_x4(bf[g], addr);
            }
            #pragma unroll
            for (int mi = 0; mi < 2; ++mi)
                #pragma unroll
                for (int g = 0; g < 4; ++g) {
                    mma16816(acc[mi][2*g],   ah[mi], bf[g][0], bf[g][1]);
                    mma16816(acc[mi][2*g+1], ah[mi], bf[g][2], bf[g][3]);
                }
        }
        __syncthreads();
        if (c + 3 < NC)
            issue_chunk(sbase, s, A, B, m0, n0, K, (c + 3) << 5, tid);
        CP_COMMIT();
        s = (s == 2) ? 0 : s + 1;
    }

    const int mbase = m0 + wm * 32;
    const int nbase = n0 + wn * 64;
    const int qr = lane >> 2;
    const int qc = (lane & 3) * 2;
    #pragma unroll
    for (int mi = 0; mi < 2; ++mi) {
        #pragma unroll
        for (int half = 0; half < 2; ++half) {
            const int r = mbase + mi * 16 + half * 8 + qr;
            #pragma unroll
            for (int ni = 0; ni < 8; ++ni) {
                const int cc = nbase + ni * 8 + qc;
                float v0 = acc[mi][ni][half * 2] + bias[cc];
                float v1 = acc[mi][ni][half * 2 + 1] + bias[cc + 1];
                size_t base = (size_t)r * N + cc;
                __half2 rh = *(const __half2*)(res + base);
                float2 rr = __half22float2(rh);
                v0 += rr.x; v1 += rr.y;
                *(float2*)(outf + base) = make_float2(v0, v1);
            }
        }
    }
}

// ---------------- MMA CSWin attention (ex2.f16x2, constant-fragment lsum) ----
#define A_SK   0
#define A_VT   20480
#define A_VN   37376
#define A_CWS  57856
#define A_CB   59008
#define ASMEM  59136

__device__ __forceinline__ int lmap(int s, int br, int widx) {
    return br == 0 ? (((s >> 1) << 7) + (widx << 1) + (s & 1))
                   : ((((widx << 1) + (s >> 7)) << 7) + (s & 127));
}

__global__ void __launch_bounds__(256, 2) attn_mma(
    const __half* __restrict__ qkv,
    const float* __restrict__ cw0, const float* __restrict__ cb0,
    const float* __restrict__ cw1, const float* __restrict__ cb1,
    __half* __restrict__ att)
{
    extern __shared__ char smem[];
    const uint32_t sb = smem_u32(smem);
    const int tid  = threadIdx.x;
    const int lane = tid & 31;
    const int w    = tid >> 5;
    const int win  = blockIdx.x;
    const int head = blockIdx.y;
    const int br   = blockIdx.z;
    const int b    = win >> 6;
    const int widx = win & 63;
    const int cbase = br * 64 + head * 32;

    // ---- phase 1: stage Q, build (scale*log2e)-folded A-fragments -----------
    #pragma unroll
    for (int i = 0; i < 4; ++i) {
        int flat = tid + (i << 8);
        int s = flat >> 2, part = flat & 3;
        size_t grow = (size_t)(b * 16384 + lmap(s, br, widx)) * 384 + cbase + part * 8;
        cp_async16(sb + A_SK + s * 80 + part * 16, qkv + grow);
    }
    CP_COMMIT(); CP_WAIT0();
    __syncthreads();

    const int ra  = lane & 15;
    const int kha = lane >> 4;
    const float scl = 0.17677669529663687f * 1.4426950408889634f;
    const __half2 sch = __floats2half2_rn(scl, scl);
    const uint32_t scu = *(const uint32_t*)&sch;
    uint32_t aq[2][2][4];
    #pragma unroll
    for (int mi = 0; mi < 2; ++mi)
        #pragma unroll
        for (int kk = 0; kk < 2; ++kk) {
            uint32_t addr = sb + A_SK + (w*32 + mi*16 + ra) * 80 + kk*32 + kha*16;
            ldm_x4(aq[mi][kk], addr);
            #pragma unroll
            for (int j = 0; j < 4; ++j) aq[mi][kk][j] = h2mul(aq[mi][kk][j], scu);
        }
    __syncthreads();

    // ---- phase 2: load K, V (transposed + normal), conv weights -------------
    #pragma unroll
    for (int i = 0; i < 4; ++i) {
        int flat = tid + (i << 8);
        int s = flat >> 2, part = flat & 3;
        size_t grow = (size_t)(b * 16384 + lmap(s, br, widx)) * 384 + cbase + 128 + part * 8;
        cp_async16(sb + A_SK + s * 80 + part * 16, qkv + grow);
    }
    CP_COMMIT();
    {
        const int s = tid;
        size_t grow = (size_t)(b * 16384 + lmap(s, br, widx)) * 384 + cbase + 256;
        __half vh[32];
        #pragma unroll
        for (int u = 0; u < 4; ++u)
            *(uint4*)&vh[u*8] = *(const uint4*)(qkv + grow + u*8);
        __half* th = (__half*)(smem + A_VT);
        #pragma unroll
        for (int d = 0; d < 32; ++d)
            th[d * 264 + s] = vh[d];
        #pragma unroll
        for (int u = 0; u < 4; ++u)
            *(uint4*)(smem + A_VN + s * 80 + u * 16) = *(uint4*)&vh[u*8];
    }
    {
        const float* cw = br ? cw1 : cw0;
        const float* cb = br ? cb1 : cb0;
        float* cws = (float*)(smem + A_CWS);
        float* cbs = (float*)(smem + A_CB);
        for (int i = tid; i < 288; i += 256) {
            int d = i / 9, tap = i % 9;
            cws[tap * 32 + d] = cw[head * 288 + i];
        }
        if (tid < 32) cbs[tid] = cb[head * 32 + tid];
    }
    CP_WAIT0();
    __syncthreads();

    // ---- flash loop: joint-mi S (fp16 acc), ex2.f16x2, const-fragment lsum --
    const int rb  = (lane & 7) + ((lane >> 4) << 3);
    const int khb = (lane >> 3) & 1;
    const uint32_t vones = (lane < 4) ? 0x3C003C00u : 0u;

    float oacc[2][4][4];
    float lsacc[2][4];
    #pragma unroll
    for (int i = 0; i < 2; ++i) {
        #pragma unroll
        for (int j = 0; j < 4; ++j) {
            lsacc[i][j] = 0.f;
            #pragma unroll
            for (int k = 0; k < 4; ++k) oacc[i][j][k] = 0.f;
        }
    }

    for (int cc = 0; cc < 4; ++cc) {
        uint32_t sacc_h[2][8][2];
        #pragma unroll
        for (int mi = 0; mi < 2; ++mi)
            #pragma unroll
            for (int j = 0; j < 8; ++j) { sacc_h[mi][j][0] = 0u; sacc_h[mi][j][1] = 0u; }

        #pragma unroll
        for (int kk = 0; kk < 2; ++kk) {
            uint32_t bh[4][4];
            #pragma unroll
            for (int g = 0; g < 4; ++g) {
                uint32_t addr = sb + A_SK + (cc*64 + g*16 + rb) * 80 + kk*32 + khb*16;
                ldm_x4(bh[g], addr);
            }
            #pragma unroll
            for (int mi = 0; mi < 2; ++mi)
                #pragma unroll
                for (int g = 0; g < 4; ++g) {
                    mma16816_h(sacc_h[mi][2*g],   aq[mi][kk], bh[g][0], bh[g][1]);
                    mma16816_h(sacc_h[mi][2*g+1], aq[mi][kk], bh[g][2], bh[g][3]);
                }
        }

        #pragma unroll
        for (int mi = 0; mi < 2; ++mi)
            #pragma unroll
            for (int nt = 0; nt < 8; ++nt) {
                ex2_h2(sacc_h[mi][nt][0]);
                ex2_h2(sacc_h[mi][nt][1]);
            }

        #pragma unroll
        for (int kt = 0; kt < 4; ++kt) {
            uint32_t vb[2][4];
            #pragma unroll
            for (int g = 0; g < 2; ++g) {
                uint32_t addr = sb + A_VT + (g*16 + rb) * 528 + (cc*64 + kt*16) * 2 + khb*16;
                ldm_x4(vb[g], addr);
            }
            #pragma unroll
            for (int mi = 0; mi < 2; ++mi) {
                uint32_t pa[4] = { sacc_h[mi][2*kt][0],   sacc_h[mi][2*kt][1],
                                   sacc_h[mi][2*kt+1][0], sacc_h[mi][2*kt+1][1] };
                #pragma unroll
                for (int g = 0; g < 2; ++g) {
                    mma16816(oacc[mi][2*g],   pa, vb[g][0], vb[g][1]);
                    mma16816(oacc[mi][2*g+1], pa, vb[g][2], vb[g][3]);
                }
                mma16816(lsacc[mi], pa, vones, vones);
            }
        }
    }

    // ---- finalize: 1/lsum, bias, LePE, scatter store -------------------------
    const int qr = lane >> 2;
    const int qc = (lane & 3) * 2;
    float ls[4];
    #pragma unroll
    for (int mi = 0; mi < 2; ++mi)
        #pragma unroll
        for (int rh = 0; rh < 2; ++rh) {
            float v = __shfl_sync(0xffffffffu, lsacc[mi][rh*2], lane & ~3);
            ls[mi*2 + rh] = 1.0f / v;
        }

    const float* cws = (const float*)(smem + A_CWS);
    const float* cbs = (const float*)(smem + A_CB);
    const int Ws = (br == 0) ? 2 : 128;
    const int Hs = (br == 0) ? 128 : 2;

    #pragma unroll
    for (int mi = 0; mi < 2; ++mi)
        #pragma unroll
        for (int rh = 0; rh < 2; ++rh) {
            const int r  = mi*2 + rh;
            const int tl = w*32 + mi*16 + rh*8 + qr;
            const int yy = (br == 0) ? (tl >> 1) : (tl >> 7);
            const int xx = tl & (Ws - 1);
            const int lq = lmap(tl, br, widx);
            const size_t ob = ((size_t)(b * 16384 + lq)) * 128 + cbase;
            #pragma unroll
            for (int nt = 0; nt < 4; ++nt) {
                const int d0 = nt*8 + qc;
                float v0 = oacc[mi][nt][rh*2]   * ls[r] + cbs[d0];
                float v1 = oacc[mi][nt][rh*2+1] * ls[r] + cbs[d0+1];
                #pragma unroll
                for (int dy = -1; dy <= 1; ++dy) {
                    int ny = yy + dy;
                    if (ny < 0 || ny >= Hs) continue;
                    #pragma unroll
                    for (int dx = -1; dx <= 1; ++dx) {
                        int nx = xx + dx;
                        if (nx < 0 || nx >= Ws) continue;
                        int tp  = ny * Ws + nx;
                        int tap = (dy + 1) * 3 + (dx + 1);
                        float2 ww = *(const float2*)&cws[tap*32 + d0];
                        __half2 hv = *(const __half2*)(smem + A_VN + tp*80 + d0*2);
                        float2 vv = __half22float2(hv);
                        v0 += ww.x * vv.x;
                        v1 += ww.y * vv.y;
                    }
                }
                *(uint32_t*)(att + ob + d0) = pack_h2(v0, v1);
            }
        }
}

// ---------------- launch ----------------------------------------------------
extern "C" void kernel_launch(void* const* d_in, const int* in_sizes, int n_in,
                              void* d_out, int out_size)
{
    const float* x      = (const float*)d_in[0];
    const float* ln1_g  = (const float*)d_in[1];
    const float* ln1_b  = (const float*)d_in[2];
    const float* w_qkv  = (const float*)d_in[3];
    const float* w_proj = (const float*)d_in[4];
    const float* b_proj = (const float*)d_in[5];
    const float* cw0    = (const float*)d_in[6];
    const float* cb0    = (const float*)d_in[7];
    const float* cw1    = (const float*)d_in[8];
    const float* cb1    = (const float*)d_in[9];
    const float* ln2_g  = (const float*)d_in[10];
    const float* ln2_b  = (const float*)d_in[11];
    const float* w1     = (const float*)d_in[12];
    const float* b1     = (const float*)d_in[13];
    const float* w2     = (const float*)d_in[14];
    const float* b2     = (const float*)d_in[15];
    float* out = (float*)d_out;

    __half *ln, *qkv, *att, *y, *ln2, *h, *wq_h, *wp_h, *w1_h, *w2_h;
    cudaGetSymbolAddress((void**)&ln,   g_ln);
    cudaGetSymbolAddress((void**)&qkv,  g_qkv);
    cudaGetSymbolAddress((void**)&att,  g_att);
    cudaGetSymbolAddress((void**)&y,    g_y);
    cudaGetSymbolAddress((void**)&ln2,  g_ln2);
    cudaGetSymbolAddress((void**)&h,    g_h);
    cudaGetSymbolAddress((void**)&wq_h, g_wq_h);
    cudaGetSymbolAddress((void**)&wp_h, g_wp_h);
    cudaGetSymbolAddress((void**)&w1_h, g_w1_h);
    cudaGetSymbolAddress((void**)&w2_h, g_w2_h);

    cudaFuncSetAttribute(mma_gemm128, cudaFuncAttributeMaxDynamicSharedMemorySize, G128SMEM);
    cudaFuncSetAttribute(mma_gemm,    cudaFuncAttributeMaxDynamicSharedMemorySize, GSMEM3);
    cudaFuncSetAttribute(attn_mma,    cudaFuncAttributeMaxDynamicSharedMemorySize, ASMEM);

    // 1) fused LN1 + weight conversion (single launch)
    ln_conv_kernel<<<16384 + 768, 256>>>(x, ln1_g, ln1_b, ln,
                                         w_qkv, w_proj, w1, w2,
                                         wq_h, wp_h, w1_h, w2_h);
    // 2) QKV -> fp16 (REVERSED m-order: reads ln where LN1 last wrote)
    mma_gemm128<<<dim3(3, 1024), 256, G128SMEM>>>(ln, wq_h, nullptr, nullptr,
                                                  nullptr, nullptr, nullptr, qkv,
                                                  384, 3, 1);
    // 3) MMA attention + LePE -> fp16
    attn_mma<<<dim3(512, 2, 2), 256, ASMEM>>>(qkv, cw0, cb0, cw1, cb1, att);
    // 4) proj + bias + residual(x) -> y fp16 AND fused LN2 -> fp16 (ascending)
    mma_gemm128<<<dim3(1, 1024), 256, G128SMEM>>>(att, wp_h, b_proj, x,
                                                  ln2_g, ln2_b, y, ln2,
                                                  128, 4, 0);
    // 5) fc1 + bias + GELU -> fp16 (REVERSED m-order)
    mma_gemm128<<<dim3(4, 1024), 256, G128SMEM>>>(ln2, w1_h, b1, nullptr,
                                                  nullptr, nullptr, nullptr, h,
                                                  512, 2, 1);
    // 6) fc2 + bias + residual(y fp16) -> out (ascending, 3-stage K=512)
    mma_gemm<<<dim3(1, 1024), 256, GSMEM3>>>(h, w2_h, b2, y, out, 128, 512);
}